// round 3
// baseline (speedup 1.0000x reference)
#include <cuda_runtime.h>
#include <math.h>

#define MD 1024
#define ND 4096
#define BD 16
#define KK 32
#define KK2 64
#define SMX 512
#define NITER 8
#define MSPLIT 8
#define TOLSQ (1e-6f * 1e-6f)

// ---------------- persistent device state ----------------
__device__ __align__(16) float g_rT[MD][BD];                 // residual transposed [m][b]
__device__ __align__(16) float g_partial[MSPLIT][BD][ND];    // proxy partial sums
__device__ unsigned char g_support[BD][ND];
__device__ int   g_suplist[BD][SMX];
__device__ int   g_scount[BD];
__device__ int   g_sold[BD];
__device__ int   g_done[BD];
__device__ __align__(16) float g_P[BD][SMX][MD];             // packed support columns
__device__ __align__(16) float g_G[BD][SMX][SMX];            // Gram (insertion order)
__device__ __align__(16) float g_H[BD][SMX][SMX];            // running inverse of G
__device__ float g_c[BD][SMX];                               // A_sub^T y
__device__ float g_sol[BD][SMX];
__device__ __align__(16) float g_T1[BD][SMX][KK2];           // H*G12
__device__ __align__(16) float g_T2[BD][SMX][KK2];           // T1*Sinv
__device__ float g_S[BD][KK2][KK2];
__device__ float g_Sinv[BD][KK2][KK2];
__device__ int   g_xcols[BD][KK];
__device__ float g_xvals[BD][KK];

// ---------------- init ----------------
__global__ void k_init(const float* __restrict__ meas) {
    int i = blockIdx.x * blockDim.x + threadIdx.x;
    int stride = gridDim.x * blockDim.x;
    for (int t = i; t < BD * ND; t += stride) g_support[t / ND][t % ND] = 0;
    if (i < BD * MD) { int b = i / MD, m = i % MD; g_rT[m][b] = meas[b * MD + m]; }
    if (i < BD) { g_scount[i] = 0; g_sold[i] = 0; g_done[i] = 0; }
}

// ---------------- proxy = A^T r, m-split partials ----------------
// grid (4, 4, MSPLIT), block 256
__global__ void k_proxy(const float* __restrict__ A) {
    int t  = threadIdx.x;
    int n0 = (blockIdx.x * 256 + t) * 4;
    int bg = blockIdx.y * 4;
    int mz = blockIdx.z;
    int m0 = mz * (MD / MSPLIT);
    float acc[4][4] = {};
    #pragma unroll 4
    for (int mm = 0; mm < MD / MSPLIT; mm++) {
        int m = m0 + mm;
        float4 a  = *(const float4*)(A + (size_t)m * ND + n0);
        float4 rv = *(const float4*)(&g_rT[m][bg]);
        acc[0][0] = fmaf(a.x, rv.x, acc[0][0]); acc[0][1] = fmaf(a.y, rv.x, acc[0][1]);
        acc[0][2] = fmaf(a.z, rv.x, acc[0][2]); acc[0][3] = fmaf(a.w, rv.x, acc[0][3]);
        acc[1][0] = fmaf(a.x, rv.y, acc[1][0]); acc[1][1] = fmaf(a.y, rv.y, acc[1][1]);
        acc[1][2] = fmaf(a.z, rv.y, acc[1][2]); acc[1][3] = fmaf(a.w, rv.y, acc[1][3]);
        acc[2][0] = fmaf(a.x, rv.z, acc[2][0]); acc[2][1] = fmaf(a.y, rv.z, acc[2][1]);
        acc[2][2] = fmaf(a.z, rv.z, acc[2][2]); acc[2][3] = fmaf(a.w, rv.z, acc[2][3]);
        acc[3][0] = fmaf(a.x, rv.w, acc[3][0]); acc[3][1] = fmaf(a.y, rv.w, acc[3][1]);
        acc[3][2] = fmaf(a.z, rv.w, acc[3][2]); acc[3][3] = fmaf(a.w, rv.w, acc[3][3]);
    }
    #pragma unroll
    for (int bb = 0; bb < 4; bb++) {
        float4 v = make_float4(acc[bb][0], acc[bb][1], acc[bb][2], acc[bb][3]);
        *(float4*)(&g_partial[mz][bg + bb][n0]) = v;
    }
}

// ---------------- reduce partials + top-64 + support update ----------------
// grid BD, block 512
__global__ void k_topk(void) {
    int b = blockIdx.x;
    if (g_done[b]) return;
    __shared__ float sp[ND];
    __shared__ float wv[16];
    __shared__ int   wi[16];
    int t = threadIdx.x;
    const int BT = 512;
    for (int n = t; n < ND; n += BT) {
        float s = 0.f;
        #pragma unroll
        for (int ms = 0; ms < MSPLIT; ms++) s += g_partial[ms][b][n];
        sp[n] = fabsf(s);
    }
    __syncthreads();
    int cnt = 0, sold = 0;
    if (t == 0) { cnt = g_scount[b]; sold = cnt; }
    for (int pass = 0; pass < 2 * KK; pass++) {
        float bv = -1.f; int bi = ND;
        for (int n = t; n < ND; n += BT) {
            float v = sp[n];
            if (v > bv) { bv = v; bi = n; }
        }
        #pragma unroll
        for (int off = 16; off; off >>= 1) {
            float ov = __shfl_down_sync(0xffffffffu, bv, off);
            int   oi = __shfl_down_sync(0xffffffffu, bi, off);
            if (ov > bv || (ov == bv && oi < bi)) { bv = ov; bi = oi; }
        }
        if ((t & 31) == 0) { wv[t >> 5] = bv; wi[t >> 5] = bi; }
        __syncthreads();
        if (t < 32) {
            bv = (t < 16) ? wv[t] : -2.f;
            bi = (t < 16) ? wi[t] : ND;
            #pragma unroll
            for (int off = 8; off; off >>= 1) {
                float ov = __shfl_down_sync(0xffffffffu, bv, off);
                int   oi = __shfl_down_sync(0xffffffffu, bi, off);
                if (ov > bv || (ov == bv && oi < bi)) { bv = ov; bi = oi; }
            }
            if (t == 0) {
                sp[bi] = -1.f;
                if (!g_support[b][bi]) {
                    g_support[b][bi] = 1;
                    g_suplist[b][cnt] = bi;
                    cnt++;
                }
            }
        }
        __syncthreads();
    }
    if (t == 0) { g_sold[b] = sold; g_scount[b] = cnt; }
}

// ---------------- pack new columns + c = P_new^T y ----------------
// grid (BD, KK2), block 128
__global__ void k_pack(const float* __restrict__ A, const float* __restrict__ meas) {
    int b = blockIdx.x;
    if (g_done[b]) return;
    int so = g_sold[b], s = g_scount[b];
    int p = so + blockIdx.y;
    if (p >= s) return;
    int col = g_suplist[b][p];
    int t = threadIdx.x;
    float acc = 0.f;
    for (int m = t; m < MD; m += 128) {
        float v = A[(size_t)m * ND + col];
        g_P[b][p][m] = v;
        acc = fmaf(v, meas[b * MD + m], acc);
    }
    __shared__ float red[4];
    #pragma unroll
    for (int off = 16; off; off >>= 1) acc += __shfl_down_sync(0xffffffffu, acc, off);
    if ((t & 31) == 0) red[t >> 5] = acc;
    __syncthreads();
    if (t == 0) g_c[b][p] = red[0] + red[1] + red[2] + red[3];
}

// ---------------- Gram new rows: G[new, 0..s) = Pnew @ Pall^T ----------------
// grid (BD, SMX/32), block 256
__global__ void k_gram(void) {
    int b = blockIdx.x;
    if (g_done[b]) return;
    int so = g_sold[b], s = g_scount[b], nn = s - so;
    if (nn == 0) return;
    int i0 = blockIdx.y * 32;
    if (i0 >= s) return;
    __shared__ float As[64][33], Bs[32][33];
    int t = threadIdx.x;
    int r = t & 63, cg = t >> 6;
    float acc[8] = {};
    for (int k0 = 0; k0 < MD; k0 += 32) {
        for (int idx = t; idx < 64 * 32; idx += 256) {
            int rr = idx >> 5, kk = idx & 31;
            As[rr][kk] = (rr < nn) ? g_P[b][so + rr][k0 + kk] : 0.f;
        }
        for (int idx = t; idx < 32 * 32; idx += 256) {
            int rr = idx >> 5, kk = idx & 31;
            Bs[rr][kk] = (i0 + rr < s) ? g_P[b][i0 + rr][k0 + kk] : 0.f;
        }
        __syncthreads();
        #pragma unroll
        for (int kk = 0; kk < 32; kk++) {
            float av = As[r][kk];
            #pragma unroll
            for (int cc = 0; cc < 8; cc++) acc[cc] = fmaf(av, Bs[cg + 4 * cc][kk], acc[cc]);
        }
        __syncthreads();
    }
    if (r < nn) {
        #pragma unroll
        for (int cc = 0; cc < 8; cc++) {
            int i = i0 + cg + 4 * cc;
            if (i < s) { float v = acc[cc]; g_G[b][so + r][i] = v; g_G[b][i][so + r] = v; }
        }
    }
}

// ---------------- T1 = H_old @ G12  (so x 64) ----------------
// grid (BD, SMX/32), block 256
__global__ void k_T1(void) {
    int b = blockIdx.x;
    if (g_done[b]) return;
    int so = g_sold[b], s = g_scount[b];
    int r0 = blockIdx.y * 32;
    if (r0 >= so) return;
    __shared__ float Hs[32][33], Gs[32][65];
    int t = threadIdx.x;
    int r = t & 31, cg = t >> 5;
    float acc[8] = {};
    for (int k0 = 0; k0 < so; k0 += 32) {
        for (int idx = t; idx < 32 * 32; idx += 256) {
            int rr = idx >> 5, kk = idx & 31;
            Hs[rr][kk] = (r0 + rr < so && k0 + kk < so) ? g_H[b][r0 + rr][k0 + kk] : 0.f;
        }
        for (int idx = t; idx < 32 * 64; idx += 256) {
            int kk = idx >> 6, c = idx & 63;
            Gs[kk][c] = (k0 + kk < so && so + c < s) ? g_G[b][k0 + kk][so + c] : 0.f;
        }
        __syncthreads();
        #pragma unroll
        for (int kk = 0; kk < 32; kk++) {
            float hv = Hs[r][kk];
            #pragma unroll
            for (int cc = 0; cc < 8; cc++) acc[cc] = fmaf(hv, Gs[kk][cg + 8 * cc], acc[cc]);
        }
        __syncthreads();
    }
    if (r0 + r < so) {
        #pragma unroll
        for (int cc = 0; cc < 8; cc++) g_T1[b][r0 + r][cg + 8 * cc] = acc[cc];
    }
}

// ---------------- S = G22 - G21 @ T1  (nn x nn) ----------------
// grid BD, block 256
__global__ void k_S(void) {
    int b = blockIdx.x;
    if (g_done[b]) return;
    int so = g_sold[b], s = g_scount[b], nn = s - so;
    if (nn == 0) return;
    __shared__ float Gs[64][65], Ts[64][65];
    int t = threadIdx.x;
    int i = t & 63, jg = t >> 6;
    float acc[16] = {};
    for (int k0 = 0; k0 < so; k0 += 64) {
        for (int idx = t; idx < 64 * 64; idx += 256) {
            int rr = idx >> 6, kk = idx & 63;
            Gs[rr][kk] = (rr < nn && k0 + kk < so) ? g_G[b][so + rr][k0 + kk] : 0.f;
        }
        for (int idx = t; idx < 64 * 64; idx += 256) {
            int kk = idx >> 6, j = idx & 63;
            Ts[kk][j] = (k0 + kk < so) ? g_T1[b][k0 + kk][j] : 0.f;
        }
        __syncthreads();
        #pragma unroll
        for (int kk = 0; kk < 64; kk++) {
            float gv = Gs[i][kk];
            #pragma unroll
            for (int jj = 0; jj < 16; jj++) acc[jj] = fmaf(gv, Ts[kk][jg * 16 + jj], acc[jj]);
        }
        __syncthreads();
    }
    if (i < nn) {
        #pragma unroll
        for (int jj = 0; jj < 16; jj++) {
            int j = jg * 16 + jj;
            if (j < nn) g_S[b][i][j] = g_G[b][so + i][so + j] - acc[jj];
        }
    }
}

// ---------------- Sinv = inverse(S) via Gauss-Jordan (SPD, no pivoting) ----------------
// grid BD, block 256
__global__ void k_Sinv(void) {
    int b = blockIdx.x;
    if (g_done[b]) return;
    int so = g_sold[b], s = g_scount[b], nn = s - so;
    if (nn == 0) return;
    __shared__ float aug[KK2][2 * KK2 + 1];
    __shared__ float fcol[KK2];
    int t = threadIdx.x;
    for (int idx = t; idx < KK2 * 2 * KK2; idx += 256) {
        int i = idx >> 7, j = idx & 127;
        if (i < nn)
            aug[i][j] = (j < nn) ? g_S[b][i][j] : ((j - nn == i) ? 1.f : 0.f);
    }
    __syncthreads();
    for (int j = 0; j < nn; j++) {
        float piv = aug[j][j];
        __syncthreads();
        for (int c = t; c < 2 * nn; c += 256) aug[j][c] = aug[j][c] / piv;
        __syncthreads();
        for (int i = t; i < nn; i += 256) fcol[i] = (i == j) ? 0.f : aug[i][j];
        __syncthreads();
        for (int idx = t; idx < nn * 128; idx += 256) {
            int i = idx >> 7, c = idx & 127;
            if (c < 2 * nn) aug[i][c] = fmaf(-fcol[i], aug[j][c], aug[i][c]);
        }
        __syncthreads();
    }
    for (int idx = t; idx < nn * KK2; idx += 256) {
        int i = idx >> 6, jj = idx & 63;
        if (jj < nn) g_Sinv[b][i][jj] = aug[i][nn + jj];
    }
}

// ---------------- T2 = T1 @ Sinv  (so x 64) ----------------
// grid (BD, SMX/32), block 256
__global__ void k_T2(void) {
    int b = blockIdx.x;
    if (g_done[b]) return;
    int so = g_sold[b], s = g_scount[b], nn = s - so;
    if (nn == 0) return;
    int r0 = blockIdx.y * 32;
    if (r0 >= so) return;
    __shared__ float Ts[32][65], Ss[64][65];
    int t = threadIdx.x;
    int r = t & 31, cg = t >> 5;
    for (int idx = t; idx < 32 * 64; idx += 256) {
        int rr = idx >> 6, k = idx & 63;
        Ts[rr][k] = (r0 + rr < so) ? g_T1[b][r0 + rr][k] : 0.f;
    }
    for (int idx = t; idx < 64 * 64; idx += 256) {
        int k = idx >> 6, j = idx & 63;
        Ss[k][j] = (k < nn && j < nn) ? g_Sinv[b][k][j] : 0.f;
    }
    __syncthreads();
    float acc[8] = {};
    #pragma unroll
    for (int kk = 0; kk < 64; kk++) {
        float tv = Ts[r][kk];
        #pragma unroll
        for (int cc = 0; cc < 8; cc++) acc[cc] = fmaf(tv, Ss[kk][cg + 8 * cc], acc[cc]);
    }
    if (r0 + r < so) {
        #pragma unroll
        for (int cc = 0; cc < 8; cc++) g_T2[b][r0 + r][cg + 8 * cc] = acc[cc];
    }
}

// ---------------- H11 += T2 @ T1^T ----------------
// grid (BD, 16, 16), block 256
__global__ void k_H11(void) {
    int b = blockIdx.x;
    if (g_done[b]) return;
    int so = g_sold[b], s = g_scount[b], nn = s - so;
    if (nn == 0) return;
    int r0 = blockIdx.y * 32, c0 = blockIdx.z * 32;
    if (r0 >= so || c0 >= so) return;
    __shared__ float T2s[32][65], T1s[32][65];
    int t = threadIdx.x;
    int r = t & 31, cg = t >> 5;
    for (int idx = t; idx < 32 * 64; idx += 256) {
        int rr = idx >> 6, k = idx & 63;
        T2s[rr][k] = (r0 + rr < so) ? g_T2[b][r0 + rr][k] : 0.f;
        T1s[rr][k] = (c0 + rr < so) ? g_T1[b][c0 + rr][k] : 0.f;
    }
    __syncthreads();
    float acc[4] = {};
    #pragma unroll
    for (int kk = 0; kk < 64; kk++) {
        float tv = T2s[r][kk];
        #pragma unroll
        for (int cc = 0; cc < 4; cc++) acc[cc] = fmaf(tv, T1s[cg + 8 * cc][kk], acc[cc]);
    }
    if (r0 + r < so) {
        #pragma unroll
        for (int cc = 0; cc < 4; cc++) {
            int c = c0 + cg + 8 * cc;
            if (c < so) g_H[b][r0 + r][c] += acc[cc];
        }
    }
}

// ---------------- H12/H21 = -T2 ; H22 = Sinv ----------------
// grid BD, block 512
__global__ void k_H12(void) {
    int b = blockIdx.x;
    if (g_done[b]) return;
    int so = g_sold[b], s = g_scount[b], nn = s - so;
    if (nn == 0) return;
    int t = threadIdx.x;
    for (int idx = t; idx < so * KK2; idx += 512) {
        int i = idx >> 6, c = idx & 63;
        if (c < nn) {
            float v = -g_T2[b][i][c];
            g_H[b][i][so + c] = v;
            g_H[b][so + c][i] = v;
        }
    }
    for (int idx = t; idx < KK2 * KK2; idx += 512) {
        int i = idx >> 6, c = idx & 63;
        if (i < nn && c < nn) g_H[b][so + i][so + c] = g_Sinv[b][i][c];
    }
}

// ---------------- sol = H c, one refinement: sol += H (c - G sol) ----------------
// grid BD, block 512
__global__ void k_solve(void) {
    int b = blockIdx.x;
    if (g_done[b]) return;
    int s = g_scount[b];
    int t = threadIdx.x;
    __shared__ float cs[SMX], sl[SMX], rs[SMX];
    if (t < s) cs[t] = g_c[b][t];
    __syncthreads();
    float acc = 0.f;
    for (int j = 0; j < s; j++) acc = fmaf(g_H[b][j][t], cs[j], acc);  // H symmetric
    sl[t] = acc;
    __syncthreads();
    acc = 0.f;
    for (int j = 0; j < s; j++) acc = fmaf(g_G[b][j][t], sl[j], acc);  // G symmetric
    rs[t] = (t < s) ? (cs[t] - acc) : 0.f;
    __syncthreads();
    acc = 0.f;
    for (int j = 0; j < s; j++) acc = fmaf(g_H[b][j][t], rs[j], acc);
    if (t < s) g_sol[b][t] = sl[t] + acc;
}

// ---------------- top-32 of |sol| + residual update + conv check ----------------
// grid BD, block 512
__global__ void k_thresh(const float* __restrict__ meas) {
    int b = blockIdx.x;
    if (g_done[b]) return;
    int s = g_scount[b];
    int t = threadIdx.x;
    __shared__ float av[SMX];
    __shared__ int   acol[SMX];
    __shared__ float wv[16]; __shared__ int wc[16]; __shared__ int wp[16];
    __shared__ float pv[KK]; __shared__ int pp[KK];
    __shared__ float rn[16];
    if (t < s) { av[t] = fabsf(g_sol[b][t]); acol[t] = g_suplist[b][t]; }
    else       { av[t] = -1.f; acol[t] = 0x7fffffff; }
    __syncthreads();
    for (int pass = 0; pass < KK; pass++) {
        float v = av[t]; int c = acol[t]; int p = t;
        #pragma unroll
        for (int off = 16; off; off >>= 1) {
            float ov = __shfl_down_sync(0xffffffffu, v, off);
            int   oc = __shfl_down_sync(0xffffffffu, c, off);
            int   op = __shfl_down_sync(0xffffffffu, p, off);
            if (ov > v || (ov == v && oc < c)) { v = ov; c = oc; p = op; }
        }
        if ((t & 31) == 0) { wv[t >> 5] = v; wc[t >> 5] = c; wp[t >> 5] = p; }
        __syncthreads();
        if (t < 32) {
            v = (t < 16) ? wv[t] : -2.f;
            c = (t < 16) ? wc[t] : 0x7fffffff;
            p = (t < 16) ? wp[t] : 0;
            #pragma unroll
            for (int off = 8; off; off >>= 1) {
                float ov = __shfl_down_sync(0xffffffffu, v, off);
                int   oc = __shfl_down_sync(0xffffffffu, c, off);
                int   op = __shfl_down_sync(0xffffffffu, p, off);
                if (ov > v || (ov == v && oc < c)) { v = ov; c = oc; p = op; }
            }
            if (t == 0) { pv[pass] = g_sol[b][p]; pp[pass] = p; av[p] = -1.f; }
        }
        __syncthreads();
    }
    if (t < KK) { g_xcols[b][t] = g_suplist[b][pp[t]]; g_xvals[b][t] = pv[t]; }
    float nrm = 0.f;
    for (int m = t; m < MD; m += 512) {
        float r = meas[b * MD + m];
        #pragma unroll
        for (int j = 0; j < KK; j++) r = fmaf(-pv[j], g_P[b][pp[j]][m], r);
        g_rT[m][b] = r;
        nrm = fmaf(r, r, nrm);
    }
    #pragma unroll
    for (int off = 16; off; off >>= 1) nrm += __shfl_down_sync(0xffffffffu, nrm, off);
    if ((t & 31) == 0) rn[t >> 5] = nrm;
    __syncthreads();
    if (t == 0) {
        float tot = 0.f;
        #pragma unroll
        for (int w = 0; w < 16; w++) tot += rn[w];
        if (tot < TOLSQ) g_done[b] = 1;
    }
}

// ---------------- output: zero + scatter ----------------
// grid BD, block 512
__global__ void k_out(float* __restrict__ out) {
    int b = blockIdx.x, t = threadIdx.x;
    for (int n = t; n < ND; n += 512) out[(size_t)b * ND + n] = 0.f;
    __syncthreads();
    if (t < KK) out[(size_t)b * ND + g_xcols[b][t]] = g_xvals[b][t];
}

extern "C" void kernel_launch(void* const* d_in, const int* in_sizes, int n_in,
                              void* d_out, int out_size) {
    const float* meas = (const float*)d_in[0];
    const float* A    = (const float*)d_in[1];
    if (n_in >= 2 && in_sizes[0] != BD * MD) {  // defensive: detect order by size
        meas = (const float*)d_in[1];
        A    = (const float*)d_in[0];
    }
    float* out = (float*)d_out;

    k_init<<<256, 256>>>(meas);
    for (int it = 0; it < NITER; it++) {
        k_proxy<<<dim3(4, 4, MSPLIT), 256>>>(A);
        k_topk<<<BD, 512>>>();
        k_pack<<<dim3(BD, KK2), 128>>>(A, meas);
        k_gram<<<dim3(BD, SMX / 32), 256>>>();
        k_T1<<<dim3(BD, SMX / 32), 256>>>();
        k_S<<<BD, 256>>>();
        k_Sinv<<<BD, 256>>>();
        k_T2<<<dim3(BD, SMX / 32), 256>>>();
        k_H11<<<dim3(BD, 16, 16), 256>>>();
        k_H12<<<BD, 512>>>();
        k_solve<<<BD, 512>>>();
        k_thresh<<<BD, 512>>>(meas);
    }
    k_out<<<BD, 512>>>(out);
}

// round 4
// speedup vs baseline: 1.0084x; 1.0084x over previous
#include <cuda_runtime.h>
#include <math.h>

#define MD 1024
#define ND 4096
#define BD 16
#define KK 32
#define KK2 64
#define SMX 512
#define NITER 8
#define MSPLIT 8
#define TOLSQ (1e-6f * 1e-6f)

// ---------------- persistent device state ----------------
__device__ __align__(16) float g_AT[ND][MD];                 // A transposed
__device__ __align__(16) float g_rT[MD][BD];                 // residual transposed [m][b]
__device__ __align__(16) float g_partial[MSPLIT][BD][ND];    // proxy partial sums
__device__ unsigned char g_support[BD][ND];
__device__ int   g_suplist[BD][SMX];
__device__ int   g_scount[BD];
__device__ int   g_sold[BD];
__device__ int   g_done[BD];
__device__ __align__(16) float g_P[BD][SMX][MD];             // packed support columns
__device__ __align__(16) float g_G[BD][SMX][SMX];            // Gram (insertion order)
__device__ __align__(16) float g_H[BD][SMX][SMX];            // running inverse of G
__device__ float g_c[BD][SMX];                               // A_sub^T y
__device__ __align__(16) float g_T1[BD][SMX][KK2];           // H*G12 (pad cols zeroed)
__device__ __align__(16) float g_T2[BD][SMX][KK2];           // T1*Sinv
__device__ float g_Sinv[BD][KK2][KK2];                       // padded-identity inverse
__device__ int   g_xcols[BD][KK];
__device__ float g_xvals[BD][KK];

// ---------------- one-time: transpose A ----------------
__global__ void k_transpose(const float* __restrict__ A) {
    __shared__ float tile[32][33];
    int nb = blockIdx.x * 32, mb = blockIdx.y * 32;
    int tx = threadIdx.x, ty = threadIdx.y;
    for (int i = ty; i < 32; i += 8)
        tile[i][tx] = A[(size_t)(mb + i) * ND + nb + tx];
    __syncthreads();
    for (int i = ty; i < 32; i += 8)
        g_AT[nb + i][mb + tx] = tile[tx][i];
}

// ---------------- init ----------------
__global__ void k_init(const float* __restrict__ meas) {
    int i = blockIdx.x * blockDim.x + threadIdx.x;
    int stride = gridDim.x * blockDim.x;
    for (int t = i; t < BD * ND; t += stride) g_support[t / ND][t % ND] = 0;
    if (i < BD * MD) { int b = i / MD, m = i % MD; g_rT[m][b] = meas[b * MD + m]; }
    if (i < BD) { g_scount[i] = 0; g_sold[i] = 0; g_done[i] = 0; }
}

// ---------------- proxy = A^T r, m-split partials ----------------
// grid (4, 4, MSPLIT), block 256
__global__ void k_proxy(const float* __restrict__ A) {
    int t  = threadIdx.x;
    int n0 = (blockIdx.x * 256 + t) * 4;
    int bg = blockIdx.y * 4;
    int mz = blockIdx.z;
    int m0 = mz * (MD / MSPLIT);
    float acc[4][4] = {};
    #pragma unroll 4
    for (int mm = 0; mm < MD / MSPLIT; mm++) {
        int m = m0 + mm;
        float4 a  = *(const float4*)(A + (size_t)m * ND + n0);
        float4 rv = *(const float4*)(&g_rT[m][bg]);
        acc[0][0] = fmaf(a.x, rv.x, acc[0][0]); acc[0][1] = fmaf(a.y, rv.x, acc[0][1]);
        acc[0][2] = fmaf(a.z, rv.x, acc[0][2]); acc[0][3] = fmaf(a.w, rv.x, acc[0][3]);
        acc[1][0] = fmaf(a.x, rv.y, acc[1][0]); acc[1][1] = fmaf(a.y, rv.y, acc[1][1]);
        acc[1][2] = fmaf(a.z, rv.y, acc[1][2]); acc[1][3] = fmaf(a.w, rv.y, acc[1][3]);
        acc[2][0] = fmaf(a.x, rv.z, acc[2][0]); acc[2][1] = fmaf(a.y, rv.z, acc[2][1]);
        acc[2][2] = fmaf(a.z, rv.z, acc[2][2]); acc[2][3] = fmaf(a.w, rv.z, acc[2][3]);
        acc[3][0] = fmaf(a.x, rv.w, acc[3][0]); acc[3][1] = fmaf(a.y, rv.w, acc[3][1]);
        acc[3][2] = fmaf(a.z, rv.w, acc[3][2]); acc[3][3] = fmaf(a.w, rv.w, acc[3][3]);
    }
    #pragma unroll
    for (int bb = 0; bb < 4; bb++) {
        float4 v = make_float4(acc[bb][0], acc[bb][1], acc[bb][2], acc[bb][3]);
        *(float4*)(&g_partial[mz][bg + bb][n0]) = v;
    }
}

// ---------------- radix-select top-64 + support update ----------------
// grid BD, block 512
__global__ void k_topk(void) {
    const int BT = 512;
    int b = blockIdx.x;
    if (g_done[b]) return;
    __shared__ unsigned keys[ND];
    __shared__ int hist[4][256];
    __shared__ unsigned sh_pref; __shared__ int sh_need;
    __shared__ int wsum[16];
    __shared__ int sh_eqbase, sh_appbase, sh_sold;
    int t = threadIdx.x;
    int lane = t & 31, wd = t >> 5;
    for (int n = t; n < ND; n += BT) {
        float s = 0.f;
        #pragma unroll
        for (int ms = 0; ms < MSPLIT; ms++) s += g_partial[ms][b][n];
        keys[n] = __float_as_uint(fabsf(s));
    }
    if (t == 0) sh_sold = g_scount[b];
    __syncthreads();
    unsigned pref = 0; int need = 2 * KK;
    for (int shift = 24; shift >= 0; shift -= 8) {
        unsigned mhi = (shift == 24) ? 0u : (0xFFFFFFFFu << (shift + 8));
        for (int i = t; i < 4 * 256; i += BT) hist[i >> 8][i & 255] = 0;
        __syncthreads();
        int hs = wd & 3;
        for (int n = t; n < ND; n += BT) {
            unsigned k = keys[n];
            if ((k & mhi) == pref) atomicAdd(&hist[hs][(k >> shift) & 255], 1);
        }
        __syncthreads();
        if (t < 256) hist[0][t] += hist[1][t] + hist[2][t] + hist[3][t];
        __syncthreads();
        if (t == 0) {
            int cum = 0, bs = 0;
            for (int bb = 255; bb >= 0; bb--) { cum += hist[0][bb]; if (cum >= need) { bs = bb; break; } }
            sh_pref = pref | ((unsigned)bs << shift);
            sh_need = need - (cum - hist[0][bs]);
        }
        __syncthreads();
        pref = sh_pref; need = sh_need;
        __syncthreads();
    }
    unsigned T = pref;
    if (t == 0) { sh_eqbase = 0; sh_appbase = sh_sold; }
    __syncthreads();
    for (int chunk = 0; chunk < ND / BT; chunk++) {
        int n = chunk * BT + t;
        unsigned k = keys[n];
        bool isgt = k > T;
        bool iseq = (k == T);
        unsigned beq = __ballot_sync(0xffffffffu, iseq);
        if (lane == 0) wsum[wd] = __popc(beq);
        __syncthreads();
        int eqpre = 0, eqtot = 0;
        #pragma unroll
        for (int w = 0; w < 16; w++) { int v = wsum[w]; if (w < wd) eqpre += v; eqtot += v; }
        int eqrank = sh_eqbase + eqpre + __popc(beq & ((1u << lane) - 1));
        bool sel = isgt || (iseq && eqrank < need);
        bool app = sel && (g_support[b][n] == 0);
        unsigned bap = __ballot_sync(0xffffffffu, app);
        __syncthreads();
        if (lane == 0) wsum[wd] = __popc(bap);
        __syncthreads();
        int appre = 0, aptot = 0;
        #pragma unroll
        for (int w = 0; w < 16; w++) { int v = wsum[w]; if (w < wd) appre += v; aptot += v; }
        if (app) g_suplist[b][sh_appbase + appre + __popc(bap & ((1u << lane) - 1))] = n;
        if (sel) g_support[b][n] = 1;
        __syncthreads();
        if (t == 0) { sh_eqbase += eqtot; sh_appbase += aptot; }
        __syncthreads();
    }
    if (t == 0) { g_sold[b] = sh_sold; g_scount[b] = sh_appbase; }
}

// ---------------- pack new columns (coalesced via AT) + c = P_new^T y ----------------
// grid (BD, KK2), block 128
__global__ void k_pack(const float* __restrict__ meas) {
    int b = blockIdx.x;
    if (g_done[b]) return;
    int so = g_sold[b], s = g_scount[b];
    int p = so + blockIdx.y;
    if (p >= s) return;
    int col = g_suplist[b][p];
    int t = threadIdx.x;
    const float4* Acol = (const float4*)g_AT[col];
    const float4* Y    = (const float4*)(meas + (size_t)b * MD);
    float4* Pd = (float4*)g_P[b][p];
    float acc = 0.f;
    #pragma unroll
    for (int i = 0; i < 2; i++) {
        int idx = t + i * 128;
        float4 v = Acol[idx]; float4 yv = Y[idx];
        Pd[idx] = v;
        acc = fmaf(v.x, yv.x, fmaf(v.y, yv.y, fmaf(v.z, yv.z, fmaf(v.w, yv.w, acc))));
    }
    __shared__ float red[4];
    #pragma unroll
    for (int off = 16; off; off >>= 1) acc += __shfl_down_sync(0xffffffffu, acc, off);
    if ((t & 31) == 0) red[t >> 5] = acc;
    __syncthreads();
    if (t == 0) g_c[b][p] = red[0] + red[1] + red[2] + red[3];
}

// ---------------- Gram new rows: 64x64 tiles, 4x4 accs ----------------
// grid (BD, SMX/64), block 256
__global__ void k_gram(void) {
    int b = blockIdx.x;
    if (g_done[b]) return;
    int so = g_sold[b], s = g_scount[b], nn = s - so;
    if (nn == 0) return;
    int c0 = blockIdx.y * 64;
    if (c0 >= s) return;
    __shared__ float As[64][65], Bs[64][65];
    int t = threadIdx.x;
    int ty = t >> 4, tx = t & 15;
    float acc[4][4] = {};
    for (int k0 = 0; k0 < MD; k0 += 64) {
        for (int idx = t; idx < 64 * 64; idx += 256) {
            int rr = idx >> 6, kk = idx & 63;
            As[rr][kk] = (rr < nn) ? g_P[b][so + rr][k0 + kk] : 0.f;
            Bs[rr][kk] = (c0 + rr < s) ? g_P[b][c0 + rr][k0 + kk] : 0.f;
        }
        __syncthreads();
        #pragma unroll 8
        for (int k = 0; k < 64; k++) {
            float rv[4], cv[4];
            #pragma unroll
            for (int i = 0; i < 4; i++) rv[i] = As[ty * 4 + i][k];
            #pragma unroll
            for (int j = 0; j < 4; j++) cv[j] = Bs[tx * 4 + j][k];
            #pragma unroll
            for (int i = 0; i < 4; i++)
                #pragma unroll
                for (int j = 0; j < 4; j++) acc[i][j] = fmaf(rv[i], cv[j], acc[i][j]);
        }
        __syncthreads();
    }
    #pragma unroll
    for (int i = 0; i < 4; i++) {
        int r = ty * 4 + i; if (r >= nn) continue;
        #pragma unroll
        for (int j = 0; j < 4; j++) {
            int c = c0 + tx * 4 + j; if (c >= s) continue;
            float v = acc[i][j];
            g_G[b][so + r][c] = v;
            g_G[b][c][so + r] = v;
        }
    }
}

// ---------------- T1 = H_old @ G12 : 64x64 tiles (pad cols -> 0) ----------------
// grid (BD, SMX/64), block 256
__global__ void k_T1(void) {
    int b = blockIdx.x;
    if (g_done[b]) return;
    int so = g_sold[b], s = g_scount[b];
    int r0 = blockIdx.y * 64;
    if (r0 >= so) return;
    __shared__ float As[64][65], Bs[64][65];
    int t = threadIdx.x;
    int ty = t >> 4, tx = t & 15;
    float acc[4][4] = {};
    for (int k0 = 0; k0 < so; k0 += 64) {
        for (int idx = t; idx < 64 * 64; idx += 256) {
            int rr = idx >> 6, kk = idx & 63;
            As[rr][kk] = (r0 + rr < so && k0 + kk < so) ? g_H[b][r0 + rr][k0 + kk] : 0.f;
            int c = idx & 63, k2 = idx >> 6;
            Bs[c][k2] = (k0 + k2 < so && so + c < s) ? g_G[b][k0 + k2][so + c] : 0.f;
        }
        __syncthreads();
        #pragma unroll 8
        for (int k = 0; k < 64; k++) {
            float rv[4], cv[4];
            #pragma unroll
            for (int i = 0; i < 4; i++) rv[i] = As[ty * 4 + i][k];
            #pragma unroll
            for (int j = 0; j < 4; j++) cv[j] = Bs[tx * 4 + j][k];
            #pragma unroll
            for (int i = 0; i < 4; i++)
                #pragma unroll
                for (int j = 0; j < 4; j++) acc[i][j] = fmaf(rv[i], cv[j], acc[i][j]);
        }
        __syncthreads();
    }
    #pragma unroll
    for (int i = 0; i < 4; i++) {
        int r = r0 + ty * 4 + i; if (r >= so) continue;
        #pragma unroll
        for (int j = 0; j < 4; j++) g_T1[b][r][tx * 4 + j] = acc[i][j];
    }
}

// ---------------- fused: S = G22 - G21 T1 (smem) -> GJ inverse -> Sinv, H22 ----------------
// grid BD, block 512
__global__ void k_SSinv(void) {
    int b = blockIdx.x;
    if (g_done[b]) return;
    int so = g_sold[b], s = g_scount[b], nn = s - so;
    if (nn == 0) return;
    __shared__ float Gs[64][65], Ts[64][65];
    __shared__ float pivrow[128], fcol[64], sh_piv;
    int t = threadIdx.x;
    // --- S = G22 - G21 @ T1 ---
    int i = t >> 3, jg = t & 7;
    float accs[8] = {};
    for (int k0 = 0; k0 < so; k0 += 64) {
        for (int idx = t; idx < 64 * 64; idx += 512) {
            int rr = idx >> 6, kk = idx & 63;
            Gs[rr][kk] = (rr < nn && k0 + kk < so) ? g_G[b][so + rr][k0 + kk] : 0.f;
            int j = idx & 63, k2 = idx >> 6;
            Ts[k2][j] = (k0 + k2 < so) ? g_T1[b][k0 + k2][j] : 0.f;
        }
        __syncthreads();
        #pragma unroll 8
        for (int k = 0; k < 64; k++) {
            float gv = Gs[i][k];
            #pragma unroll
            for (int jj = 0; jj < 8; jj++) accs[jj] = fmaf(gv, Ts[k][jg * 8 + jj], accs[jj]);
        }
        __syncthreads();
    }
    // write padded S into Gs (identity pad keeps GJ stable + pads drop out)
    #pragma unroll
    for (int jj = 0; jj < 8; jj++) {
        int j = jg * 8 + jj;
        float v;
        if (i < nn && j < nn) v = g_G[b][so + i][so + j] - accs[jj];
        else v = (i == j) ? 1.f : 0.f;
        Gs[i][j] = v;
    }
    __syncthreads();
    // --- Gauss-Jordan: 64 rows x 8 threads, 16 aug cols in regs ---
    int row = t >> 3, cg = t & 7;
    float a[16];
    #pragma unroll
    for (int cc = 0; cc < 16; cc++) {
        int c = cg * 16 + cc;
        a[cc] = (c < 64) ? Gs[row][c] : ((c - 64 == row) ? 1.f : 0.f);
    }
    __syncthreads();
    for (int j = 0; j < 64; j++) {
        if (row == j && cg == (j >> 4)) sh_piv = a[j & 15];
        __syncthreads();
        float inv = 1.f / sh_piv;
        if (row == j) {
            #pragma unroll
            for (int cc = 0; cc < 16; cc++) { a[cc] *= inv; pivrow[cg * 16 + cc] = a[cc]; }
        }
        if (cg == (j >> 4)) fcol[row] = a[j & 15];
        __syncthreads();
        float f = (row == j) ? 0.f : fcol[row];
        #pragma unroll
        for (int cc = 0; cc < 16; cc++) a[cc] = fmaf(-f, pivrow[cg * 16 + cc], a[cc]);
    }
    __syncthreads();
    #pragma unroll
    for (int cc = 0; cc < 16; cc++) {
        int c = cg * 16 + cc;
        if (c >= 64) {
            int j = c - 64;
            g_Sinv[b][row][j] = a[cc];
            if (row < nn && j < nn) g_H[b][so + row][so + j] = a[cc];
        }
    }
}

// ---------------- T2 = T1 @ Sinv (+ H12/H21 epilogue) ----------------
// grid (BD, SMX/64), block 256
__global__ void k_T2(void) {
    int b = blockIdx.x;
    if (g_done[b]) return;
    int so = g_sold[b], s = g_scount[b], nn = s - so;
    if (nn == 0) return;
    int r0 = blockIdx.y * 64;
    if (r0 >= so) return;
    __shared__ float As[64][65], Bs[64][65];
    int t = threadIdx.x;
    int ty = t >> 4, tx = t & 15;
    for (int idx = t; idx < 64 * 64; idx += 256) {
        int rr = idx >> 6, kk = idx & 63;
        As[rr][kk] = (r0 + rr < so) ? g_T1[b][r0 + rr][kk] : 0.f;
        int c = idx & 63, k2 = idx >> 6;
        Bs[c][k2] = g_Sinv[b][k2][c];
    }
    __syncthreads();
    float acc[4][4] = {};
    #pragma unroll 8
    for (int k = 0; k < 64; k++) {
        float rv[4], cv[4];
        #pragma unroll
        for (int i = 0; i < 4; i++) rv[i] = As[ty * 4 + i][k];
        #pragma unroll
        for (int j = 0; j < 4; j++) cv[j] = Bs[tx * 4 + j][k];
        #pragma unroll
        for (int i = 0; i < 4; i++)
            #pragma unroll
            for (int j = 0; j < 4; j++) acc[i][j] = fmaf(rv[i], cv[j], acc[i][j]);
    }
    #pragma unroll
    for (int i = 0; i < 4; i++) {
        int r = r0 + ty * 4 + i; if (r >= so) continue;
        #pragma unroll
        for (int j = 0; j < 4; j++) {
            int cx = tx * 4 + j;
            float v = acc[i][j];
            g_T2[b][r][cx] = v;
            if (cx < nn) { g_H[b][r][so + cx] = -v; g_H[b][so + cx][r] = -v; }
        }
    }
}

// ---------------- H11 += T2 @ T1^T ----------------
// grid (BD, 8, 8), block 256
__global__ void k_H11(void) {
    int b = blockIdx.x;
    if (g_done[b]) return;
    int so = g_sold[b], s = g_scount[b], nn = s - so;
    if (nn == 0) return;
    int r0 = blockIdx.y * 64, c0 = blockIdx.z * 64;
    if (r0 >= so || c0 >= so) return;
    __shared__ float As[64][65], Bs[64][65];
    int t = threadIdx.x;
    int ty = t >> 4, tx = t & 15;
    for (int idx = t; idx < 64 * 64; idx += 256) {
        int rr = idx >> 6, kk = idx & 63;
        As[rr][kk] = (r0 + rr < so) ? g_T2[b][r0 + rr][kk] : 0.f;
        Bs[rr][kk] = (c0 + rr < so) ? g_T1[b][c0 + rr][kk] : 0.f;
    }
    __syncthreads();
    float acc[4][4] = {};
    #pragma unroll 8
    for (int k = 0; k < 64; k++) {
        float rv[4], cv[4];
        #pragma unroll
        for (int i = 0; i < 4; i++) rv[i] = As[ty * 4 + i][k];
        #pragma unroll
        for (int j = 0; j < 4; j++) cv[j] = Bs[tx * 4 + j][k];
        #pragma unroll
        for (int i = 0; i < 4; i++)
            #pragma unroll
            for (int j = 0; j < 4; j++) acc[i][j] = fmaf(rv[i], cv[j], acc[i][j]);
    }
    #pragma unroll
    for (int i = 0; i < 4; i++) {
        int r = r0 + ty * 4 + i; if (r >= so) continue;
        #pragma unroll
        for (int j = 0; j < 4; j++) {
            int c = c0 + tx * 4 + j; if (c >= so) continue;
            g_H[b][r][c] += acc[i][j];
        }
    }
}

// ---------------- fused solve (+1 refinement) + radix top-32 + residual ----------------
// grid BD, block 512
__global__ void k_solvethresh(const float* __restrict__ meas) {
    int b = blockIdx.x;
    if (g_done[b]) return;
    int s = g_scount[b];
    int t = threadIdx.x;
    int lane = t & 31, wd = t >> 5;
    __shared__ float cs[SMX], sl[SMX], rs[SMX];
    if (t < s) cs[t] = g_c[b][t]; else cs[t] = 0.f;
    __syncthreads();
    float acc = 0.f;
    #pragma unroll 4
    for (int j = 0; j < s; j++) acc = fmaf(g_H[b][j][t], cs[j], acc);   // H symmetric
    sl[t] = acc;
    __syncthreads();
    acc = 0.f;
    #pragma unroll 4
    for (int j = 0; j < s; j++) acc = fmaf(g_G[b][j][t], sl[j], acc);   // G symmetric
    rs[t] = (t < s) ? (cs[t] - acc) : 0.f;
    __syncthreads();
    acc = 0.f;
    #pragma unroll 4
    for (int j = 0; j < s; j++) acc = fmaf(g_H[b][j][t], rs[j], acc);
    float solv = sl[t] + acc;
    // --- radix select top-32 of |solv| over slots < s ---
    __shared__ int hist[256];
    __shared__ unsigned sh_pref; __shared__ int sh_need;
    unsigned key = (t < s) ? __float_as_uint(fabsf(solv)) : 0u;
    unsigned pref = 0; int need = KK;
    for (int shift = 24; shift >= 0; shift -= 8) {
        unsigned mhi = (shift == 24) ? 0u : (0xFFFFFFFFu << (shift + 8));
        if (t < 256) hist[t] = 0;
        __syncthreads();
        if ((key & mhi) == pref) atomicAdd(&hist[(key >> shift) & 255], 1);
        __syncthreads();
        if (t == 0) {
            int cum = 0, bs = 0;
            for (int bb = 255; bb >= 0; bb--) { cum += hist[bb]; if (cum >= need) { bs = bb; break; } }
            sh_pref = pref | ((unsigned)bs << shift);
            sh_need = need - (cum - hist[bs]);
        }
        __syncthreads();
        pref = sh_pref; need = sh_need;
        __syncthreads();
    }
    unsigned T = pref;
    // --- tie resolution by smallest column id ---
    __shared__ int eqsl[SMX]; __shared__ int neq;
    __shared__ unsigned char self_[SMX];
    bool isgt = (key > T) && (t < s);
    bool iseq = (key == T) && (t < s);
    self_[t] = isgt ? 1 : 0;
    if (t == 0) neq = 0;
    __syncthreads();
    if (iseq) { int p = atomicAdd(&neq, 1); eqsl[p] = t; }
    __syncthreads();
    if (t == 0) {
        for (int r = 0; r < need; r++) {
            int bestc = 0x7fffffff, bi = -1;
            for (int q = 0; q < neq; q++) {
                int slot = eqsl[q];
                if (!self_[slot]) { int c = g_suplist[b][slot]; if (c < bestc) { bestc = c; bi = slot; } }
            }
            if (bi >= 0) self_[bi] = 1;
        }
    }
    __syncthreads();
    // --- gather selected 32 in slot order ---
    __shared__ int wsum[16]; __shared__ float pv[KK]; __shared__ int pp[KK];
    __shared__ float rn[16];
    bool sel = self_[t] != 0;
    unsigned bsel = __ballot_sync(0xffffffffu, sel);
    if (lane == 0) wsum[wd] = __popc(bsel);
    __syncthreads();
    int pre = 0;
    #pragma unroll
    for (int w = 0; w < 16; w++) if (w < wd) pre += wsum[w];
    int rank = pre + __popc(bsel & ((1u << lane) - 1));
    if (sel) { pp[rank] = t; pv[rank] = solv; }
    __syncthreads();
    if (t < KK) { g_xcols[b][t] = g_suplist[b][pp[t]]; g_xvals[b][t] = pv[t]; }
    // --- residual update + norm ---
    float nrm = 0.f;
    for (int m = t; m < MD; m += 512) {
        float r = meas[(size_t)b * MD + m];
        #pragma unroll
        for (int j = 0; j < KK; j++) r = fmaf(-pv[j], g_P[b][pp[j]][m], r);
        g_rT[m][b] = r;
        nrm = fmaf(r, r, nrm);
    }
    #pragma unroll
    for (int off = 16; off; off >>= 1) nrm += __shfl_down_sync(0xffffffffu, nrm, off);
    if (lane == 0) rn[wd] = nrm;
    __syncthreads();
    if (t == 0) {
        float tot = 0.f;
        #pragma unroll
        for (int w = 0; w < 16; w++) tot += rn[w];
        if (tot < TOLSQ) g_done[b] = 1;
    }
}

// ---------------- output: zero + scatter ----------------
__global__ void k_out(float* __restrict__ out) {
    int b = blockIdx.x, t = threadIdx.x;
    for (int n = t; n < ND; n += 512) out[(size_t)b * ND + n] = 0.f;
    __syncthreads();
    if (t < KK) out[(size_t)b * ND + g_xcols[b][t]] = g_xvals[b][t];
}

extern "C" void kernel_launch(void* const* d_in, const int* in_sizes, int n_in,
                              void* d_out, int out_size) {
    const float* meas = (const float*)d_in[0];
    const float* A    = (const float*)d_in[1];
    if (n_in >= 2 && in_sizes[0] != BD * MD) {
        meas = (const float*)d_in[1];
        A    = (const float*)d_in[0];
    }
    float* out = (float*)d_out;

    k_transpose<<<dim3(ND / 32, MD / 32), dim3(32, 8)>>>(A);
    k_init<<<256, 256>>>(meas);
    for (int it = 0; it < NITER; it++) {
        k_proxy<<<dim3(4, 4, MSPLIT), 256>>>(A);
        k_topk<<<BD, 512>>>();
        k_pack<<<dim3(BD, KK2), 128>>>(meas);
        k_gram<<<dim3(BD, SMX / 64), 256>>>();
        k_T1<<<dim3(BD, SMX / 64), 256>>>();
        k_SSinv<<<BD, 512>>>();
        k_T2<<<dim3(BD, SMX / 64), 256>>>();
        k_H11<<<dim3(BD, 8, 8), 256>>>();
        k_solvethresh<<<BD, 512>>>(meas);
    }
    k_out<<<BD, 512>>>(out);
}